// round 1
// baseline (speedup 1.0000x reference)
#include <cuda_runtime.h>

// ---------------------------------------------------------------------------
// PatchTokenizer: hierarchical mask selection + compacted patch gathers.
//
// Output layout (all float32, tuple order of the reference):
//   [0]  resized0 : 32768 x 768      = 25165824
//   [1]  resized1 :  8192 x 768      =  6291456
//   [2]  resized2 :  2048 x 768      =  1572864
//   [3]  fulls0   :  8192 x 4 x 768  = 25165824
//   [4]  fulls1   :  2048 x 16 x 768 = 25165824
//   [5]  mask0    : 32768
//   [6]  mask1    :  8192
//   [7]  mask2    :  2048
//   [8]  counts   : 3
//   [9]  output_mask : 43040
//   [10] seqlens  : 32
//   [11] cu_seqlens : 33
//   [12] max seqlen : 1
//   [13] retained_frac : 1
// total = 83447910 floats
// ---------------------------------------------------------------------------

#define BB 32

#define OFF1 25165824LL
#define OFF2 31457280LL
#define OFF3 33030144LL
#define OFF4 58195968LL
#define OFF5 83361792LL
#define OFF6 83394560LL
#define OFF7 83402752LL
#define OFF8 83404800LL
#define OFF9 83404803LL
#define OFF10 83447843LL
#define OFF11 83447875LL
#define OFF12 83447908LL
#define OFF13 83447909LL

// scratch (allocation-free rule: __device__ globals)
__device__ unsigned char g_m0[32768], g_m1[8192], g_m2[2048];
__device__ int g_rank0[32768], g_rank1[8192], g_rank2[2048];
__device__ int g_sel0[32768], g_sel1[8192], g_sel2[2048];
__device__ int g_cnt[3];

template <int N>
__device__ __forceinline__ void scan_mask(const unsigned char* m, int* rank,
                                          int* sel, int* total, int* sPart) {
    const int tid = threadIdx.x;
    const int CH = N / 1024;
    const int base = tid * CH;
    int s = 0;
#pragma unroll
    for (int k = 0; k < CH; k++) s += m[base + k];
    sPart[tid] = s;
    __syncthreads();
    for (int off = 1; off < 1024; off <<= 1) {
        int add = (tid >= off) ? sPart[tid - off] : 0;
        __syncthreads();
        sPart[tid] += add;
        __syncthreads();
    }
    int r = sPart[tid] - s;  // exclusive prefix for this thread's chunk
#pragma unroll
    for (int k = 0; k < CH; k++) {
        rank[base + k] = r;
        if (m[base + k]) { sel[r] = base + k; r++; }
    }
    if (tid == 1023) *total = r;
    __syncthreads();
}

__global__ void mask_kernel(const float* __restrict__ imp0,
                            const float* __restrict__ imp1,
                            const float* __restrict__ imp2,
                            float* __restrict__ out) {
    __shared__ int sPart[1024];
    __shared__ int sc0[BB], sc01[BB];
    __shared__ int scu[BB + 1];
    const int tid = threadIdx.x;

    // ---- masks -----------------------------------------------------------
    for (int i = tid; i < 2048; i += 1024) g_m2[i] = (imp2[i] < 0.3f);
    __syncthreads();
    for (int i = tid; i < 8192; i += 1024) {
        int b = i >> 8, r = (i >> 4) & 15, c = i & 15;
        g_m1[i] = (imp1[i] < 0.5f) && !g_m2[(b << 6) + ((r >> 1) << 3) + (c >> 1)];
    }
    __syncthreads();
    for (int i = tid; i < 32768; i += 1024) {
        int b = i >> 10, r = (i >> 5) & 31, c = i & 31;
        unsigned char cov = g_m2[(b << 6) + ((r >> 2) << 3) + (c >> 2)] |
                            g_m1[(b << 8) + ((r >> 1) << 4) + (c >> 1)];
        g_m0[i] = !cov;
    }
    __syncthreads();

    // ---- scans -> sel arrays + ranks ------------------------------------
    scan_mask<32768>(g_m0, g_rank0, g_sel0, &g_cnt[0], sPart);
    scan_mask<8192>(g_m1, g_rank1, g_sel1, &g_cnt[1], sPart);
    scan_mask<2048>(g_m2, g_rank2, g_sel2, &g_cnt[2], sPart);

    // ---- per-batch bookkeeping ------------------------------------------
    if (tid == 0) {
        int cu = 0, mx = 0;
        scu[0] = 0;
        out[OFF11] = 0.0f;
        for (int b = 0; b < BB; b++) {
            int r0b = (b == BB - 1) ? g_cnt[0] : g_rank0[(b + 1) << 10];
            int r1b = (b == BB - 1) ? g_cnt[1] : g_rank1[(b + 1) << 8];
            int r2b = (b == BB - 1) ? g_cnt[2] : g_rank2[(b + 1) << 6];
            int c0 = r0b - g_rank0[b << 10];
            int c1 = r1b - g_rank1[b << 8];
            int c2 = r2b - g_rank2[b << 6];
            sc0[b] = c0;
            sc01[b] = c0 + c1;
            int sl = 1 + c0 + c1 + c2;
            if (sl > mx) mx = sl;
            out[OFF10 + b] = (float)sl;
            cu += sl;
            scu[b + 1] = cu;
            out[OFF11 + 1 + b] = (float)cu;
        }
        out[OFF8 + 0] = (float)g_cnt[0];
        out[OFF8 + 1] = (float)g_cnt[1];
        out[OFF8 + 2] = (float)g_cnt[2];
        out[OFF12] = (float)mx;
        out[OFF13] = (float)cu / 32768.0f;
    }
    __syncthreads();

    // ---- mask floats -----------------------------------------------------
    for (int i = tid; i < 32768; i += 1024) out[OFF5 + i] = g_m0[i] ? 1.0f : 0.0f;
    for (int i = tid; i < 8192; i += 1024)  out[OFF6 + i] = g_m1[i] ? 1.0f : 0.0f;
    for (int i = tid; i < 2048; i += 1024)  out[OFF7 + i] = g_m2[i] ? 1.0f : 0.0f;

    // ---- compacted output_mask ------------------------------------------
    for (int i = tid; i < 43040; i += 1024) out[OFF9 + i] = 0.0f;
    __syncthreads();
    if (tid < BB) out[OFF9 + scu[tid]] = -1.0f;
    for (int i = tid; i < 32768; i += 1024)
        if (g_m0[i]) {
            int b = i >> 10;
            out[OFF9 + scu[b] + 1 + (g_rank0[i] - g_rank0[b << 10])] = 1.0f;
        }
    for (int i = tid; i < 8192; i += 1024)
        if (g_m1[i]) {
            int b = i >> 8;
            out[OFF9 + scu[b] + 1 + sc0[b] + (g_rank1[i] - g_rank1[b << 8])] = 2.0f;
        }
    for (int i = tid; i < 2048; i += 1024)
        if (g_m2[i]) {
            int b = i >> 6;
            out[OFF9 + scu[b] + 1 + sc01[b] + (g_rank2[i] - g_rank2[b << 6])] = 3.0f;
        }
}

// ---- resized0: base-scale 16x16 patches of the original image ------------
__global__ void copy_r0(const float* __restrict__ img, float* __restrict__ out) {
    int p = blockIdx.x, t = threadIdx.x;  // 192 threads, 1 float4 each
    float4* dst = reinterpret_cast<float4*>(out + (size_t)p * 768) + t;
    if (p < g_cnt[0]) {
        int s = g_sel0[p];
        int b = s >> 10, gy = (s >> 5) & 31, gx = s & 31;
        int e = t << 2;
        int c = e >> 8, y = (e >> 4) & 15, x = e & 15;
        size_t si = (((size_t)(b * 3 + c) * 512) + gy * 16 + y) * 512 + gx * 16 + x;
        *dst = *reinterpret_cast<const float4*>(img + si);
    } else {
        *dst = make_float4(0.f, 0.f, 0.f, 0.f);
    }
}

// ---- resized1: 16x16 patches of 2x-downsampled (2x2 average) image -------
__global__ void copy_r1(const float* __restrict__ img, float* __restrict__ out) {
    int p = blockIdx.x, t = threadIdx.x;
    float4* dst = reinterpret_cast<float4*>(out + (size_t)p * 768) + t;
    if (p < g_cnt[1]) {
        int s = g_sel1[p];
        int b = s >> 8, gy = (s >> 4) & 15, gx = s & 15;
        int e = t << 2;
        int c = e >> 8, y = (e >> 4) & 15, x = e & 15;
        int R = gy * 32 + 2 * y, Cc = gx * 32 + 2 * x;
        const float* base = img + (((size_t)(b * 3 + c) * 512 + R) * 512 + Cc);
        float4 a0 = *(const float4*)base;
        float4 a1 = *(const float4*)(base + 4);
        float4 b0 = *(const float4*)(base + 512);
        float4 b1 = *(const float4*)(base + 516);
        float4 o;
        o.x = (a0.x + a0.y + b0.x + b0.y) * 0.25f;
        o.y = (a0.z + a0.w + b0.z + b0.w) * 0.25f;
        o.z = (a1.x + a1.y + b1.x + b1.y) * 0.25f;
        o.w = (a1.z + a1.w + b1.z + b1.w) * 0.25f;
        *dst = o;
    } else {
        *dst = make_float4(0.f, 0.f, 0.f, 0.f);
    }
}

// ---- resized2: 16x16 patches of 4x-downsampled image (avg of central 2x2)-
__global__ void copy_r2(const float* __restrict__ img, float* __restrict__ out) {
    int p = blockIdx.x, t = threadIdx.x;
    float4* dst = reinterpret_cast<float4*>(out + (size_t)p * 768) + t;
    if (p < g_cnt[2]) {
        int s = g_sel2[p];
        int b = s >> 6, gy = (s >> 3) & 7, gx = s & 7;
        int e = t << 2;
        int c = e >> 8, y = (e >> 4) & 15, x = e & 15;
        int R0 = gy * 64 + 4 * y + 1;
        int Cb = gx * 64 + 4 * x;
        const float* r0 = img + (((size_t)(b * 3 + c) * 512 + R0) * 512 + Cb);
        const float* r1 = r0 + 512;
        float4 q0 = *(const float4*)r0, q1 = *(const float4*)(r0 + 4);
        float4 q2 = *(const float4*)(r0 + 8), q3 = *(const float4*)(r0 + 12);
        float4 u0 = *(const float4*)r1, u1 = *(const float4*)(r1 + 4);
        float4 u2 = *(const float4*)(r1 + 8), u3 = *(const float4*)(r1 + 12);
        float4 o;
        o.x = (q0.y + q0.z + u0.y + u0.z) * 0.25f;
        o.y = (q1.y + q1.z + u1.y + u1.z) * 0.25f;
        o.z = (q2.y + q2.z + u2.y + u2.z) * 0.25f;
        o.w = (q3.y + q3.z + u3.y + u3.z) * 0.25f;
        *dst = o;
    } else {
        *dst = make_float4(0.f, 0.f, 0.f, 0.f);
    }
}

// ---- fulls0: 2x2 constituent base patches of selected scale-1 patches ----
__global__ void copy_f0(const float* __restrict__ img, float* __restrict__ out) {
    int p = blockIdx.x, t = threadIdx.x;  // 768 threads, 1 float4 each
    float4* dst = reinterpret_cast<float4*>(out + (size_t)p * 3072) + t;
    if (p < g_cnt[1]) {
        int s = g_sel1[p];
        int b = s >> 8, gy = (s >> 4) & 15, gx = s & 15;
        int e = t << 2;
        int sub = e / 768, rem = e - sub * 768;
        int c = rem >> 8, y = (rem >> 4) & 15, x = rem & 15;
        int ny = sub >> 1, nx = sub & 1;
        int R = gy * 32 + ny * 16 + y, Cc = gx * 32 + nx * 16 + x;
        *dst = *reinterpret_cast<const float4*>(
            img + (((size_t)(b * 3 + c) * 512 + R) * 512 + Cc));
    } else {
        *dst = make_float4(0.f, 0.f, 0.f, 0.f);
    }
}

// ---- fulls1: 4x4 constituent base patches of selected scale-2 patches ----
__global__ void copy_f1(const float* __restrict__ img, float* __restrict__ out) {
    int p = blockIdx.x, t = threadIdx.x;  // 1024 threads, 3 float4 each
    bool sel = p < g_cnt[2];
    int s_ = sel ? g_sel2[p] : 0;
    int b = s_ >> 6, gy = (s_ >> 3) & 7, gx = s_ & 7;
    float4* base = reinterpret_cast<float4*>(out + (size_t)p * 12288);
#pragma unroll
    for (int k = 0; k < 3; k++) {
        int i = t + k * 1024;
        if (sel) {
            int e = i << 2;
            int sub = e / 768, rem = e - sub * 768;
            int c = rem >> 8, y = (rem >> 4) & 15, x = rem & 15;
            int ny = sub >> 2, nx = sub & 3;
            int R = gy * 64 + ny * 16 + y, Cc = gx * 64 + nx * 16 + x;
            base[i] = *reinterpret_cast<const float4*>(
                img + (((size_t)(b * 3 + c) * 512 + R) * 512 + Cc));
        } else {
            base[i] = make_float4(0.f, 0.f, 0.f, 0.f);
        }
    }
}

extern "C" void kernel_launch(void* const* d_in, const int* in_sizes, int n_in,
                              void* d_out, int out_size) {
    const float* img = (const float*)d_in[0];   // images  (32,3,512,512)
    const float* i0  = (const float*)d_in[1];   // imp_s0  (32,32,32)
    const float* i1  = (const float*)d_in[2];   // imp_s1  (32,16,16)
    const float* i2  = (const float*)d_in[3];   // imp_s2  (32,8,8)
    float* out = (float*)d_out;

    mask_kernel<<<1, 1024>>>(i0, i1, i2, out);
    copy_r0<<<32768, 192>>>(img, out);
    copy_r1<<<8192, 192>>>(img, out + OFF1);
    copy_r2<<<2048, 192>>>(img, out + OFF2);
    copy_f0<<<8192, 768>>>(img, out + OFF3);
    copy_f1<<<2048, 1024>>>(img, out + OFF4);
}

// round 2
// speedup vs baseline: 1.3381x; 1.3381x over previous
#include <cuda_runtime.h>

// ---------------------------------------------------------------------------
// PatchTokenizer: hierarchical mask selection + compacted patch gathers.
// Output layout (all float32, tuple order of the reference):
//   [0]  resized0 : 32768 x 768      @ 0
//   [1]  resized1 :  8192 x 768      @ OFF1
//   [2]  resized2 :  2048 x 768      @ OFF2
//   [3]  fulls0   :  8192 x 4 x 768  @ OFF3
//   [4]  fulls1   :  2048 x 16 x 768 @ OFF4
//   [5-7] masks, [8] counts, [9] output_mask, [10] seqlens, [11] cu_seqlens,
//   [12] max, [13] retained_frac
// ---------------------------------------------------------------------------

#define BB 32

#define OFF1 25165824
#define OFF2 31457280
#define OFF3 33030144
#define OFF4 58195968
#define OFF5 83361792
#define OFF8 83404800
#define OFF9 83404803
#define OFF10 83447843
#define OFF11 83447875
#define OFF12 83447908
#define OFF13 83447909

// scratch (allocation-free rule: __device__ globals)
__device__ unsigned char g_m0[32768], g_m1[8192], g_m2[2048];
__device__ int g_rank0[32768], g_rank1[8192], g_rank2[2048];
__device__ int g_sel0[32768], g_sel1[8192], g_sel2[2048];
__device__ int g_cnt[3];
__device__ int g_scu[33], g_sc0[32], g_sc01[32];

__device__ __forceinline__ float4 zero4() { return make_float4(0.f, 0.f, 0.f, 0.f); }

template <int N>
__device__ __forceinline__ void scan_mask(const unsigned char* m, int* rank,
                                          int* sel, int* total, int* sPart) {
    const int tid = threadIdx.x;
    const int CH = N / 1024;
    const int base = tid * CH;
    int s = 0;
#pragma unroll
    for (int k = 0; k < CH; k++) s += m[base + k];
    sPart[tid] = s;
    __syncthreads();
    for (int off = 1; off < 1024; off <<= 1) {
        int add = (tid >= off) ? sPart[tid - off] : 0;
        __syncthreads();
        sPart[tid] += add;
        __syncthreads();
    }
    int r = sPart[tid] - s;
#pragma unroll
    for (int k = 0; k < CH; k++) {
        rank[base + k] = r;
        if (m[base + k]) { sel[r] = base + k; r++; }
    }
    if (tid == 1023) *total = r;
    __syncthreads();
}

__global__ void mask_kernel(const float* __restrict__ imp0,
                            const float* __restrict__ imp1,
                            const float* __restrict__ imp2,
                            float* __restrict__ out) {
    __shared__ int sPart[1024];
    const int tid = threadIdx.x;

    for (int i = tid; i < 2048; i += 1024) g_m2[i] = (imp2[i] < 0.3f);
    __syncthreads();
    for (int i = tid; i < 8192; i += 1024) {
        int b = i >> 8, r = (i >> 4) & 15, c = i & 15;
        g_m1[i] = (imp1[i] < 0.5f) && !g_m2[(b << 6) + ((r >> 1) << 3) + (c >> 1)];
    }
    __syncthreads();
    for (int i = tid; i < 32768; i += 1024) {
        int b = i >> 10, r = (i >> 5) & 31, c = i & 31;
        unsigned char cov = g_m2[(b << 6) + ((r >> 2) << 3) + (c >> 2)] |
                            g_m1[(b << 8) + ((r >> 1) << 4) + (c >> 1)];
        g_m0[i] = !cov;
    }
    __syncthreads();

    scan_mask<32768>(g_m0, g_rank0, g_sel0, &g_cnt[0], sPart);
    scan_mask<8192>(g_m1, g_rank1, g_sel1, &g_cnt[1], sPart);
    scan_mask<2048>(g_m2, g_rank2, g_sel2, &g_cnt[2], sPart);

    if (tid == 0) {
        int cu = 0, mx = 0;
        g_scu[0] = 0;
        out[OFF11] = 0.0f;
        for (int b = 0; b < BB; b++) {
            int r0b = (b == BB - 1) ? g_cnt[0] : g_rank0[(b + 1) << 10];
            int r1b = (b == BB - 1) ? g_cnt[1] : g_rank1[(b + 1) << 8];
            int r2b = (b == BB - 1) ? g_cnt[2] : g_rank2[(b + 1) << 6];
            int c0 = r0b - g_rank0[b << 10];
            int c1 = r1b - g_rank1[b << 8];
            int c2 = r2b - g_rank2[b << 6];
            g_sc0[b] = c0;
            g_sc01[b] = c0 + c1;
            int sl = 1 + c0 + c1 + c2;
            if (sl > mx) mx = sl;
            out[OFF10 + b] = (float)sl;
            cu += sl;
            g_scu[b + 1] = cu;
            out[OFF11 + 1 + b] = (float)cu;
        }
        out[OFF8 + 0] = (float)g_cnt[0];
        out[OFF8 + 1] = (float)g_cnt[1];
        out[OFF8 + 2] = (float)g_cnt[2];
        out[OFF12] = (float)mx;
        out[OFF13] = (float)cu / 32768.0f;
    }
}

// ---------------------------------------------------------------------------
// Mega kernel: five big sections + small dest-driven section, block ranges:
//   S0 r0: 3072 blocks, ITER 8   (6291456 f4)
//   S1 r1: 3072 blocks, ITER 2   (1572864 f4, 4 loads/f4)
//   S2 r2: 1536 blocks, ITER 1   (393216 f4, 8 loads/f4)
//   S3 f0: 3072 blocks, ITER 8   (6291456 f4)
//   S4 f1: 3072 blocks, ITER 8   (6291456 f4)
//   S5:    128 blocks (mask floats + output_mask, dest-driven)
// ---------------------------------------------------------------------------
#define NB0 3072
#define NB1 3072
#define NB2 1536
#define NB3 3072
#define NB4 3072
#define NB5 128
#define E0 (NB0)
#define E1 (NB0 + NB1)
#define E2 (NB0 + NB1 + NB2)
#define E3 (NB0 + NB1 + NB2 + NB3)
#define E4 (NB0 + NB1 + NB2 + NB3 + NB4)
#define NBLK (E4 + NB5)

__global__ void __launch_bounds__(256)
mega_kernel(const float* __restrict__ img, float* __restrict__ out) {
    const int bs = blockIdx.x;
    const int tid = threadIdx.x;

    if (bs < E0) {
        // ---- S0: resized0 (pure copy of 16x16 base patches) --------------
        const int cnt = g_cnt[0];
        const int base = bs * 2048 + tid;
        const float* src[8];
#pragma unroll
        for (int k = 0; k < 8; k++) {
            int i = base + k * 256;
            int p = i / 192, t4 = i - p * 192;
            if (p < cnt) {
                int s = g_sel0[p];
                int b = s >> 10, gy = (s >> 5) & 31, gx = s & 31;
                int e = t4 << 2;
                int c = e >> 8, y = (e >> 4) & 15, x = e & 15;
                src[k] = img + ((b * 3 + c) * 512 + gy * 16 + y) * 512 + gx * 16 + x;
            } else src[k] = nullptr;
        }
        float4 v[8];
#pragma unroll
        for (int k = 0; k < 8; k++)
            v[k] = src[k] ? *reinterpret_cast<const float4*>(src[k]) : zero4();
        float4* dst = reinterpret_cast<float4*>(out);
#pragma unroll
        for (int k = 0; k < 8; k++) dst[base + k * 256] = v[k];

    } else if (bs < E1) {
        // ---- S1: resized1 (2x2 average of original) -----------------------
        const int cnt = g_cnt[1];
        const int base = (bs - E0) * 512 + tid;
        const float* bp[2];
#pragma unroll
        for (int k = 0; k < 2; k++) {
            int i = base + k * 256;
            int p = i / 192, t4 = i - p * 192;
            if (p < cnt) {
                int s = g_sel1[p];
                int b = s >> 8, gy = (s >> 4) & 15, gx = s & 15;
                int e = t4 << 2;
                int c = e >> 8, y = (e >> 4) & 15, x = e & 15;
                int R = gy * 32 + 2 * y, Cc = gx * 32 + 2 * x;
                bp[k] = img + ((b * 3 + c) * 512 + R) * 512 + Cc;
            } else bp[k] = nullptr;
        }
        float4 a0[2], a1[2], b0[2], b1[2];
#pragma unroll
        for (int k = 0; k < 2; k++) {
            if (bp[k]) {
                a0[k] = *(const float4*)(bp[k]);
                a1[k] = *(const float4*)(bp[k] + 4);
                b0[k] = *(const float4*)(bp[k] + 512);
                b1[k] = *(const float4*)(bp[k] + 516);
            }
        }
        float4* dst = reinterpret_cast<float4*>(out + OFF1);
#pragma unroll
        for (int k = 0; k < 2; k++) {
            float4 o = zero4();
            if (bp[k]) {
                o.x = (a0[k].x + a0[k].y + b0[k].x + b0[k].y) * 0.25f;
                o.y = (a0[k].z + a0[k].w + b0[k].z + b0[k].w) * 0.25f;
                o.z = (a1[k].x + a1[k].y + b1[k].x + b1[k].y) * 0.25f;
                o.w = (a1[k].z + a1[k].w + b1[k].z + b1[k].w) * 0.25f;
            }
            dst[base + k * 256] = o;
        }

    } else if (bs < E2) {
        // ---- S2: resized2 (central 2x2 average, 4x downsample) ------------
        const int cnt = g_cnt[2];
        const int i = (bs - E1) * 256 + tid;
        const int p = i / 192, t4 = i - p * 192;
        float4 o = zero4();
        if (p < cnt) {
            int s = g_sel2[p];
            int b = s >> 6, gy = (s >> 3) & 7, gx = s & 7;
            int e = t4 << 2;
            int c = e >> 8, y = (e >> 4) & 15, x = e & 15;
            int R0 = gy * 64 + 4 * y + 1;
            int Cb = gx * 64 + 4 * x;
            const float* r0 = img + ((b * 3 + c) * 512 + R0) * 512 + Cb;
            const float* r1 = r0 + 512;
            float4 q0 = *(const float4*)r0, q1 = *(const float4*)(r0 + 4);
            float4 q2 = *(const float4*)(r0 + 8), q3 = *(const float4*)(r0 + 12);
            float4 u0 = *(const float4*)r1, u1 = *(const float4*)(r1 + 4);
            float4 u2 = *(const float4*)(r1 + 8), u3 = *(const float4*)(r1 + 12);
            o.x = (q0.y + q0.z + u0.y + u0.z) * 0.25f;
            o.y = (q1.y + q1.z + u1.y + u1.z) * 0.25f;
            o.z = (q2.y + q2.z + u2.y + u2.z) * 0.25f;
            o.w = (q3.y + q3.z + u3.y + u3.z) * 0.25f;
        }
        reinterpret_cast<float4*>(out + OFF2)[i] = o;

    } else if (bs < E3) {
        // ---- S3: fulls0 (2x2 constituent base patches, pure copy) ---------
        const int cnt = g_cnt[1];
        const int base = (bs - E2) * 2048 + tid;
        const float* src[8];
#pragma unroll
        for (int k = 0; k < 8; k++) {
            int i = base + k * 256;
            int p = i / 768, rf = i - p * 768;
            if (p < cnt) {
                int s = g_sel1[p];
                int b = s >> 8, gy = (s >> 4) & 15, gx = s & 15;
                int e = rf << 2;
                int sub = e / 768, rem = e - sub * 768;
                int c = rem >> 8, y = (rem >> 4) & 15, x = rem & 15;
                int ny = sub >> 1, nx = sub & 1;
                int R = gy * 32 + ny * 16 + y, Cc = gx * 32 + nx * 16 + x;
                src[k] = img + ((b * 3 + c) * 512 + R) * 512 + Cc;
            } else src[k] = nullptr;
        }
        float4 v[8];
#pragma unroll
        for (int k = 0; k < 8; k++)
            v[k] = src[k] ? *reinterpret_cast<const float4*>(src[k]) : zero4();
        float4* dst = reinterpret_cast<float4*>(out + OFF3);
#pragma unroll
        for (int k = 0; k < 8; k++) dst[base + k * 256] = v[k];

    } else if (bs < E4) {
        // ---- S4: fulls1 (4x4 constituent base patches, pure copy) ---------
        const int cnt = g_cnt[2];
        const int base = (bs - E3) * 2048 + tid;
        const float* src[8];
#pragma unroll
        for (int k = 0; k < 8; k++) {
            int i = base + k * 256;
            int p = i / 3072, rf = i - p * 3072;
            if (p < cnt) {
                int s = g_sel2[p];
                int b = s >> 6, gy = (s >> 3) & 7, gx = s & 7;
                int e = rf << 2;
                int sub = e / 768, rem = e - sub * 768;
                int c = rem >> 8, y = (rem >> 4) & 15, x = rem & 15;
                int ny = sub >> 2, nx = sub & 3;
                int R = gy * 64 + ny * 16 + y, Cc = gx * 64 + nx * 16 + x;
                src[k] = img + ((b * 3 + c) * 512 + R) * 512 + Cc;
            } else src[k] = nullptr;
        }
        float4 v[8];
#pragma unroll
        for (int k = 0; k < 8; k++)
            v[k] = src[k] ? *reinterpret_cast<const float4*>(src[k]) : zero4();
        float4* dst = reinterpret_cast<float4*>(out + OFF4);
#pragma unroll
        for (int k = 0; k < 8; k++) dst[base + k * 256] = v[k];

    } else {
        // ---- S5: mask floats + output_mask (dest-driven, no races) --------
        const int rel = bs - E4;
        const int tot = g_scu[32];
        for (int i = rel * 256 + tid; i < 86048; i += NB5 * 256) {
            if (i < 43008) {
                float v;
                if (i < 32768) v = (float)g_m0[i];
                else if (i < 40960) v = (float)g_m1[i - 32768];
                else v = (float)g_m2[i - 40960];
                out[OFF5 + i] = v;
            } else {
                int j = i - 43008;
                float v = 0.0f;
                if (j < tot) {
                    int b = 0;
                    while (g_scu[b + 1] <= j) b++;
                    int r = j - g_scu[b];
                    if (r == 0) v = -1.0f;
                    else {
                        r -= 1;
                        if (r < g_sc0[b]) v = 1.0f;
                        else if (r < g_sc01[b]) v = 2.0f;
                        else v = 3.0f;
                    }
                }
                out[OFF9 + j] = v;
            }
        }
    }
}

extern "C" void kernel_launch(void* const* d_in, const int* in_sizes, int n_in,
                              void* d_out, int out_size) {
    const float* img = (const float*)d_in[0];   // images  (32,3,512,512)
    const float* i0  = (const float*)d_in[1];   // imp_s0  (32,32,32)
    const float* i1  = (const float*)d_in[2];   // imp_s1  (32,16,16)
    const float* i2  = (const float*)d_in[3];   // imp_s2  (32,8,8)
    float* out = (float*)d_out;

    mask_kernel<<<1, 1024>>>(i0, i1, i2, out);
    mega_kernel<<<NBLK, 256>>>(img, out);
}

// round 3
// speedup vs baseline: 1.7898x; 1.3375x over previous
#include <cuda_runtime.h>

// ---------------------------------------------------------------------------
// PatchTokenizer: hierarchical mask selection + compacted patch gathers.
// Output layout (all float32, tuple order of the reference):
//   [0]  resized0 : 32768 x 768      @ 0
//   [1]  resized1 :  8192 x 768      @ OFF1
//   [2]  resized2 :  2048 x 768      @ OFF2
//   [3]  fulls0   :  8192 x 4 x 768  @ OFF3
//   [4]  fulls1   :  2048 x 16 x 768 @ OFF4
//   [5-7] masks @ OFF5, [8] counts @ OFF8, [9] output_mask @ OFF9,
//   [10] seqlens, [11] cu_seqlens, [12] max, [13] retained_frac
// ---------------------------------------------------------------------------

#define OFF1 25165824
#define OFF2 31457280
#define OFF3 33030144
#define OFF4 58195968
#define OFF5 83361792
#define OFF6 83394560
#define OFF7 83402752
#define OFF8 83404800
#define OFF9 83404803
#define OFF10 83447843
#define OFF11 83447875
#define OFF12 83447908
#define OFF13 83447909

// scratch (allocation-free rule: __device__ globals)
__device__ unsigned char g_m0[32768], g_m1[8192], g_m2[2048];
__device__ int g_lsel0[32768], g_lsel1[8192], g_lsel2[2048];  // per-batch local sel
__device__ int g_c0[32], g_c1[32], g_c2[32];                  // per-batch counts
__device__ int g_sel0[32768], g_sel1[8192], g_sel2[2048];     // global sel
__device__ int g_cnt[3];
__device__ int g_scu[33], g_sc0[32], g_sc01[32];

__device__ __forceinline__ float4 zero4() { return make_float4(0.f, 0.f, 0.f, 0.f); }

// block-wide (256 thr) exclusive scan of per-thread value v; also total.
__device__ __forceinline__ void block_scan256(int v, int tid, int* wsum,
                                              int* sTotal, int& ex, int& total) {
    __syncthreads();  // protect wsum/sTotal reuse across calls
    int lane = tid & 31, wid = tid >> 5;
    int inc = v;
#pragma unroll
    for (int o = 1; o < 32; o <<= 1) {
        int n = __shfl_up_sync(0xffffffffu, inc, o);
        if (lane >= o) inc += n;
    }
    if (lane == 31) wsum[wid] = inc;
    __syncthreads();
    if (tid < 8) {
        int w = wsum[tid], wi = w;
#pragma unroll
        for (int o = 1; o < 8; o <<= 1) {
            int n = __shfl_up_sync(0xffu, wi, o);
            if (tid >= o) wi += n;
        }
        wsum[tid] = wi - w;
        if (tid == 7) *sTotal = wi;
    }
    __syncthreads();
    ex = inc - v + wsum[wid];
    total = *sTotal;
}

// ---- Kernel A: per-batch masks + local compaction (32 blocks) -------------
__global__ void __launch_bounds__(256)
maskA_kernel(const float* __restrict__ imp1, const float* __restrict__ imp2,
             float* __restrict__ out) {
    const int b = blockIdx.x, tid = threadIdx.x;
    __shared__ unsigned char sm2[64], sm1[256];
    __shared__ int wsum[8];
    __shared__ int sTotal;

    // m2 (8x8)
    unsigned char v2 = 0;
    if (tid < 64) {
        v2 = imp2[b * 64 + tid] < 0.3f;
        sm2[tid] = v2;
        g_m2[b * 64 + tid] = v2;
        out[OFF7 + b * 64 + tid] = (float)v2;
    }
    __syncthreads();

    // m1 (16x16)
    {
        int r = tid >> 4, c = tid & 15;
        unsigned char cov2 = sm2[((r >> 1) << 3) + (c >> 1)];
        unsigned char v1 = (imp1[b * 256 + tid] < 0.5f) && !cov2;
        sm1[tid] = v1;
        g_m1[b * 256 + tid] = v1;
        out[OFF6 + b * 256 + tid] = (float)v1;
    }
    __syncthreads();

    // m0 (32x32), 4 per thread
    unsigned char v0[4];
#pragma unroll
    for (int k = 0; k < 4; k++) {
        int j = tid * 4 + k;
        int r = j >> 5, c = j & 31;
        unsigned char cov = sm2[((r >> 2) << 3) + (c >> 2)] |
                            sm1[((r >> 1) << 4) + (c >> 1)];
        v0[k] = !cov;
        g_m0[b * 1024 + j] = v0[k];
        out[OFF5 + b * 1024 + j] = (float)v0[k];
    }

    // local compaction scans
    int ex, total;
    int s0 = v0[0] + v0[1] + v0[2] + v0[3];
    block_scan256(s0, tid, wsum, &sTotal, ex, total);
    int t0 = total;
    {
        int r = ex;
#pragma unroll
        for (int k = 0; k < 4; k++)
            if (v0[k]) g_lsel0[b * 1024 + r++] = tid * 4 + k;
    }

    unsigned char v1 = sm1[tid];
    block_scan256((int)v1, tid, wsum, &sTotal, ex, total);
    int t1 = total;
    if (v1) g_lsel1[b * 256 + ex] = tid;

    block_scan256(tid < 64 ? (int)v2 : 0, tid, wsum, &sTotal, ex, total);
    int t2 = total;
    if (tid < 64 && v2) g_lsel2[b * 64 + ex] = tid;

    if (tid == 0) {
        g_c0[b] = t0;
        g_c1[b] = t1;
        g_c2[b] = t2;
        out[OFF10 + b] = (float)(1 + t0 + t1 + t2);
    }
}

// ---- Kernel B: stitch batch counts -> global offsets + sel arrays --------
__global__ void __launch_bounds__(1024)
maskB_kernel(float* __restrict__ out) {
    __shared__ int sOff0[32], sOff1[32], sOff2[32];
    __shared__ int sC0[32], sC1[32], sC2[32];
    const int tid = threadIdx.x;

    if (tid < 32) {
        int c0 = g_c0[tid], c1 = g_c1[tid], c2 = g_c2[tid];
        int sl = 1 + c0 + c1 + c2;
        int i0 = c0, i1 = c1, i2 = c2, is = sl;
#pragma unroll
        for (int o = 1; o < 32; o <<= 1) {
            int n0 = __shfl_up_sync(0xffffffffu, i0, o);
            int n1 = __shfl_up_sync(0xffffffffu, i1, o);
            int n2 = __shfl_up_sync(0xffffffffu, i2, o);
            int ns = __shfl_up_sync(0xffffffffu, is, o);
            if (tid >= o) { i0 += n0; i1 += n1; i2 += n2; is += ns; }
        }
        sOff0[tid] = i0 - c0;
        sOff1[tid] = i1 - c1;
        sOff2[tid] = i2 - c2;
        sC0[tid] = c0; sC1[tid] = c1; sC2[tid] = c2;
        g_scu[tid + 1] = is;
        g_sc0[tid] = c0;
        g_sc01[tid] = c0 + c1;
        out[OFF11 + 1 + tid] = (float)is;
        int mx = sl;
#pragma unroll
        for (int o = 16; o; o >>= 1) {
            int n = __shfl_xor_sync(0xffffffffu, mx, o);
            mx = mx > n ? mx : n;
        }
        if (tid == 0) {
            g_scu[0] = 0;
            out[OFF11] = 0.0f;
            out[OFF12] = (float)mx;
        }
        if (tid == 31) {
            g_cnt[0] = i0; g_cnt[1] = i1; g_cnt[2] = i2;
            out[OFF8 + 0] = (float)i0;
            out[OFF8 + 1] = (float)i1;
            out[OFF8 + 2] = (float)i2;
            out[OFF13] = (float)is / 32768.0f;
        }
    }
    __syncthreads();

    for (int i = tid; i < 32768; i += 1024) {
        int b = i >> 10, r = i & 1023;
        if (r < sC0[b]) g_sel0[sOff0[b] + r] = g_lsel0[i] + (b << 10);
    }
    for (int i = tid; i < 8192; i += 1024) {
        int b = i >> 8, r = i & 255;
        if (r < sC1[b]) g_sel1[sOff1[b] + r] = g_lsel1[i] + (b << 8);
    }
    for (int i = tid; i < 2048; i += 1024) {
        int b = i >> 6, r = i & 63;
        if (r < sC2[b]) g_sel2[sOff2[b] + r] = g_lsel2[i] + (b << 6);
    }
}

// ---------------------------------------------------------------------------
// Mega kernel: five big sections + output_mask section, block ranges:
// ---------------------------------------------------------------------------
#define NB0 3072
#define NB1 3072
#define NB2 1536
#define NB3 3072
#define NB4 3072
#define NB5 32
#define E0 (NB0)
#define E1 (NB0 + NB1)
#define E2 (NB0 + NB1 + NB2)
#define E3 (NB0 + NB1 + NB2 + NB3)
#define E4 (NB0 + NB1 + NB2 + NB3 + NB4)
#define NBLK (E4 + NB5)

__global__ void __launch_bounds__(256)
mega_kernel(const float* __restrict__ img, float* __restrict__ out) {
    const int bs = blockIdx.x;
    const int tid = threadIdx.x;

    if (bs < E0) {
        // ---- S0: resized0 (pure copy of 16x16 base patches) --------------
        const int cnt = g_cnt[0];
        const int base = bs * 2048 + tid;
        const float* src[8];
#pragma unroll
        for (int k = 0; k < 8; k++) {
            int i = base + k * 256;
            int p = i / 192, t4 = i - p * 192;
            if (p < cnt) {
                int s = g_sel0[p];
                int b = s >> 10, gy = (s >> 5) & 31, gx = s & 31;
                int e = t4 << 2;
                int c = e >> 8, y = (e >> 4) & 15, x = e & 15;
                src[k] = img + ((b * 3 + c) * 512 + gy * 16 + y) * 512 + gx * 16 + x;
            } else src[k] = nullptr;
        }
        float4 v[8];
#pragma unroll
        for (int k = 0; k < 8; k++)
            v[k] = src[k] ? *reinterpret_cast<const float4*>(src[k]) : zero4();
        float4* dst = reinterpret_cast<float4*>(out);
#pragma unroll
        for (int k = 0; k < 8; k++) dst[base + k * 256] = v[k];

    } else if (bs < E1) {
        // ---- S1: resized1 (2x2 average of original) -----------------------
        const int cnt = g_cnt[1];
        const int base = (bs - E0) * 512 + tid;
        const float* bp[2];
#pragma unroll
        for (int k = 0; k < 2; k++) {
            int i = base + k * 256;
            int p = i / 192, t4 = i - p * 192;
            if (p < cnt) {
                int s = g_sel1[p];
                int b = s >> 8, gy = (s >> 4) & 15, gx = s & 15;
                int e = t4 << 2;
                int c = e >> 8, y = (e >> 4) & 15, x = e & 15;
                int R = gy * 32 + 2 * y, Cc = gx * 32 + 2 * x;
                bp[k] = img + ((b * 3 + c) * 512 + R) * 512 + Cc;
            } else bp[k] = nullptr;
        }
        float4 a0[2], a1[2], b0[2], b1[2];
#pragma unroll
        for (int k = 0; k < 2; k++) {
            if (bp[k]) {
                a0[k] = *(const float4*)(bp[k]);
                a1[k] = *(const float4*)(bp[k] + 4);
                b0[k] = *(const float4*)(bp[k] + 512);
                b1[k] = *(const float4*)(bp[k] + 516);
            }
        }
        float4* dst = reinterpret_cast<float4*>(out + OFF1);
#pragma unroll
        for (int k = 0; k < 2; k++) {
            float4 o = zero4();
            if (bp[k]) {
                o.x = (a0[k].x + a0[k].y + b0[k].x + b0[k].y) * 0.25f;
                o.y = (a0[k].z + a0[k].w + b0[k].z + b0[k].w) * 0.25f;
                o.z = (a1[k].x + a1[k].y + b1[k].x + b1[k].y) * 0.25f;
                o.w = (a1[k].z + a1[k].w + b1[k].z + b1[k].w) * 0.25f;
            }
            dst[base + k * 256] = o;
        }

    } else if (bs < E2) {
        // ---- S2: resized2 (central 2x2 average, 4x downsample) ------------
        const int cnt = g_cnt[2];
        const int i = (bs - E1) * 256 + tid;
        const int p = i / 192, t4 = i - p * 192;
        float4 o = zero4();
        if (p < cnt) {
            int s = g_sel2[p];
            int b = s >> 6, gy = (s >> 3) & 7, gx = s & 7;
            int e = t4 << 2;
            int c = e >> 8, y = (e >> 4) & 15, x = e & 15;
            int R0 = gy * 64 + 4 * y + 1;
            int Cb = gx * 64 + 4 * x;
            const float* r0 = img + ((b * 3 + c) * 512 + R0) * 512 + Cb;
            const float* r1 = r0 + 512;
            float4 q0 = *(const float4*)r0, q1 = *(const float4*)(r0 + 4);
            float4 q2 = *(const float4*)(r0 + 8), q3 = *(const float4*)(r0 + 12);
            float4 u0 = *(const float4*)r1, u1 = *(const float4*)(r1 + 4);
            float4 u2 = *(const float4*)(r1 + 8), u3 = *(const float4*)(r1 + 12);
            o.x = (q0.y + q0.z + u0.y + u0.z) * 0.25f;
            o.y = (q1.y + q1.z + u1.y + u1.z) * 0.25f;
            o.z = (q2.y + q2.z + u2.y + u2.z) * 0.25f;
            o.w = (q3.y + q3.z + u3.y + u3.z) * 0.25f;
        }
        reinterpret_cast<float4*>(out + OFF2)[i] = o;

    } else if (bs < E3) {
        // ---- S3: fulls0 (2x2 constituent base patches, pure copy) ---------
        const int cnt = g_cnt[1];
        const int base = (bs - E2) * 2048 + tid;
        const float* src[8];
#pragma unroll
        for (int k = 0; k < 8; k++) {
            int i = base + k * 256;
            int p = i / 768, rf = i - p * 768;
            if (p < cnt) {
                int s = g_sel1[p];
                int b = s >> 8, gy = (s >> 4) & 15, gx = s & 15;
                int e = rf << 2;
                int sub = e / 768, rem = e - sub * 768;
                int c = rem >> 8, y = (rem >> 4) & 15, x = rem & 15;
                int ny = sub >> 1, nx = sub & 1;
                int R = gy * 32 + ny * 16 + y, Cc = gx * 32 + nx * 16 + x;
                src[k] = img + ((b * 3 + c) * 512 + R) * 512 + Cc;
            } else src[k] = nullptr;
        }
        float4 v[8];
#pragma unroll
        for (int k = 0; k < 8; k++)
            v[k] = src[k] ? *reinterpret_cast<const float4*>(src[k]) : zero4();
        float4* dst = reinterpret_cast<float4*>(out + OFF3);
#pragma unroll
        for (int k = 0; k < 8; k++) dst[base + k * 256] = v[k];

    } else if (bs < E4) {
        // ---- S4: fulls1 (4x4 constituent base patches, pure copy) ---------
        const int cnt = g_cnt[2];
        const int base = (bs - E3) * 2048 + tid;
        const float* src[8];
#pragma unroll
        for (int k = 0; k < 8; k++) {
            int i = base + k * 256;
            int p = i / 3072, rf = i - p * 3072;
            if (p < cnt) {
                int s = g_sel2[p];
                int b = s >> 6, gy = (s >> 3) & 7, gx = s & 7;
                int e = rf << 2;
                int sub = e / 768, rem = e - sub * 768;
                int c = rem >> 8, y = (rem >> 4) & 15, x = rem & 15;
                int ny = sub >> 2, nx = sub & 3;
                int R = gy * 64 + ny * 16 + y, Cc = gx * 64 + nx * 16 + x;
                src[k] = img + ((b * 3 + c) * 512 + R) * 512 + Cc;
            } else src[k] = nullptr;
        }
        float4 v[8];
#pragma unroll
        for (int k = 0; k < 8; k++)
            v[k] = src[k] ? *reinterpret_cast<const float4*>(src[k]) : zero4();
        float4* dst = reinterpret_cast<float4*>(out + OFF4);
#pragma unroll
        for (int k = 0; k < 8; k++) dst[base + k * 256] = v[k];

    } else {
        // ---- S5: compacted output_mask (dest-driven) ----------------------
        const int rel = bs - E4;
        const int tot = g_scu[32];
        for (int j = rel * 256 + tid; j < 43040; j += NB5 * 256) {
            float v = 0.0f;
            if (j < tot) {
                int b = 0;
                while (g_scu[b + 1] <= j) b++;
                int r = j - g_scu[b];
                if (r == 0) v = -1.0f;
                else {
                    r -= 1;
                    if (r < g_sc0[b]) v = 1.0f;
                    else if (r < g_sc01[b]) v = 2.0f;
                    else v = 3.0f;
                }
            }
            out[OFF9 + j] = v;
        }
    }
}

extern "C" void kernel_launch(void* const* d_in, const int* in_sizes, int n_in,
                              void* d_out, int out_size) {
    const float* img = (const float*)d_in[0];   // images  (32,3,512,512)
    const float* i1  = (const float*)d_in[2];   // imp_s1  (32,16,16)
    const float* i2  = (const float*)d_in[3];   // imp_s2  (32,8,8)
    float* out = (float*)d_out;

    maskA_kernel<<<32, 256>>>(i1, i2, out);
    maskB_kernel<<<1, 1024>>>(out);
    mega_kernel<<<NBLK, 256>>>(img, out);
}